// round 11
// baseline (speedup 1.0000x reference)
#include <cuda_runtime.h>
#include <math.h>
#include <stdint.h>

namespace {
constexpr int B = 16, T = 100, N = 128, D = 3;
constexpr int FRAMES = B * T;                 // 1600
constexpr int NIT = 2;                        // frames per block
constexpr int BLOCKS = FRAMES / NIT;          // 800
constexpr int FD = N * D;                     // 384 floats per frame
constexpr int F4 = FD / 4;                    // 96 float4 per frame
constexpr float MIN_DIST = 0.05f;
constexpr float R2 = MIN_DIST * MIN_DIST;     // 0.0025
constexpr float R2_GUARD = R2 + 1e-4f;        // slack for expansion error
constexpr int EXT = 192;                      // 128 + 64 wrap replica
}

__device__ float g_pen[BLOCKS];
__device__ float g_work[BLOCKS];
__device__ float g_stab[BLOCKS];
__device__ float g_ke0[BLOCKS];
__device__ float g_ke1[BLOCKS];
__device__ unsigned int g_count;              // zero-init; self-resetting

// volatile LDS.128 — pinned program order defeats ptxas load-sinking
__device__ __forceinline__ float4 lds128(uint32_t a) {
    float4 v;
    asm volatile("ld.shared.v4.f32 {%0,%1,%2,%3}, [%4];"
                 : "=f"(v.x), "=f"(v.y), "=f"(v.z), "=f"(v.w) : "r"(a));
    return v;
}

__global__ __launch_bounds__(256) void fused_kernel(
    const float* __restrict__ traj,
    const float* __restrict__ vel,
    const float* __restrict__ frc,
    float* __restrict__ out)
{
    const int tid = threadIdx.x;
    const int f0  = blockIdx.x * NIT;
    const int fmod = f0 % T;
    const bool needvel = (fmod == 0) | (fmod >= T - 6);   // t in {0} or >= 95

    __shared__ __align__(16) float4 sP[NIT][EXT];        // (x,y,z,|p|^2)+replica
    __shared__ __align__(16) float  sT[(NIT + 1) * FD];  // raw traj: 3 frames
    __shared__ __align__(16) float  sF[NIT * FD];        // raw frc: 2 frames
    __shared__ __align__(16) float  sV[NIT * FD];        // raw vel: 2 frames

    // ========== phase 1: single bulk LDG burst (max MLP) ==========
    {
        const float4* t4  = reinterpret_cast<const float4*>(traj);
        const float4* fr4 = reinterpret_cast<const float4*>(frc);
        const float4* v4  = reinterpret_cast<const float4*>(vel);
        float4* dT = reinterpret_cast<float4*>(sT);
        float4* dF = reinterpret_cast<float4*>(sF);
        float4* dV = reinterpret_cast<float4*>(sV);
        const int baseT = f0 * F4;
        const float4 zero = make_float4(0, 0, 0, 0);

        // traj: 3 frames = 288 float4 (guard lookahead at global end)
        dT[tid] = (baseT + tid < FRAMES * F4) ? t4[baseT + tid] : zero;
        if (tid < (NIT + 1) * F4 - 256) {
            int idx = tid + 256;
            dT[idx] = (baseT + idx < FRAMES * F4) ? t4[baseT + idx] : zero;
        }
        // frc: 2 frames = 192 float4
        if (tid < NIT * F4) dF[tid] = fr4[baseT + tid];
        // vel: uniform block predicate, same burst
        if (needvel && tid < NIT * F4) dV[tid] = v4[baseT + tid];
    }
    __syncthreads();

    // ========== phase 2: build float4 frames (+|p|^2) + cheap terms ==========
    float penacc = 0.f, wrkacc = 0.f, stabacc = 0.f, ke0acc = 0.f, ke1acc = 0.f;
    {
        const int fl = tid >> 7;               // local frame 0..1
        const int p  = tid & 127;              // point index
        const int t  = (f0 + fl) % T;

        const float x = sT[fl * FD + 3 * p];
        const float y = sT[fl * FD + 3 * p + 1];
        const float z = sT[fl * FD + 3 * p + 2];
        const float w = x * x + y * y + z * z;
        float4 v4 = make_float4(x, y, z, w);
        sP[fl][p] = v4;
        if (p < 64) sP[fl][128 + p] = v4;

        if (t < T - 1) {                       // work term from staged data
            const float nx = sT[(fl + 1) * FD + 3 * p];
            const float ny = sT[(fl + 1) * FD + 3 * p + 1];
            const float nz = sT[(fl + 1) * FD + 3 * p + 2];
            const float fx = sF[fl * FD + 3 * p];
            const float fy = sF[fl * FD + 3 * p + 1];
            const float fz = sF[fl * FD + 3 * p + 2];
            wrkacc = fx * (nx - x) + fy * (ny - y) + fz * (nz - z);
        }
        if (t == 0 || t >= T - 5) {            // boundary vel terms (smem-staged)
            const float vx = sV[fl * FD + 3 * p];
            const float vy = sV[fl * FD + 3 * p + 1];
            const float vz = sV[fl * FD + 3 * p + 2];
            const float v2 = vx * vx + vy * vy + vz * vz;
            if (t >= T - 5) {
                stabacc = sqrtf(v2);
                if (t == T - 1) ke1acc = 0.5f * v2;
            } else {
                ke0acc = 0.5f * v2;
            }
        }
    }
    __syncthreads();

    // ========== phase 3: 2-row blocked mainloop, double-buffered LDS ==========
    {
        const int fh = tid >> 7;               // this thread's frame
        const int u  = tid & 127;
        const int m  = u & 63;                 // row-pair index
        const int h  = u >> 6;                 // j-half
        const int r0 = 2 * m;
        const int jb = 1 + 32 * h;             // first owned j (row0, k offset 0)
        const float4* P = sP[fh];
        const uint32_t ca =
            (uint32_t)__cvta_generic_to_shared(P + r0 + jb);

        const float4 A  = P[r0];
        const float4 Bv = P[r0 + 1];
        const float w0 = A.w,  ax = -2.0f * A.x,  ay = -2.0f * A.y,  az = -2.0f * A.z;
        const float w1 = Bv.w, bx = -2.0f * Bv.x, by = -2.0f * Bv.y, bz = -2.0f * Bv.z;

        float4 q0[4], q1[4];
        // tail column (k = 32, row1 only) + first batch issued up front
        const float4 qt = lds128(ca + 16 * 32);
        #pragma unroll
        for (int e = 0; e < 4; ++e) q0[e] = lds128(ca + 16 * e);

        float acc0 = 1e30f, acc1 = 1e30f, acc2 = 1e30f, acc3 = 1e30f;

        #pragma unroll
        for (int b = 0; b < 8; ++b) {
            if (b < 7) {                       // prefetch next batch
                const uint32_t na = ca + 64 * (b + 1);
                if (b & 1) {
                    #pragma unroll
                    for (int e = 0; e < 4; ++e) q0[e] = lds128(na + 16 * e);
                } else {
                    #pragma unroll
                    for (int e = 0; e < 4; ++e) q1[e] = lds128(na + 16 * e);
                }
            }
            #pragma unroll
            for (int e = 0; e < 4; ++e) {
                const int k = 4 * b + e;
                const float4 qq = (b & 1) ? q1[e] : q0[e];
                float s0 = w0 + qq.w;
                s0 = fmaf(ax, qq.x, s0);
                s0 = fmaf(ay, qq.y, s0);
                s0 = fmaf(az, qq.z, s0);
                float s1 = w1 + qq.w;
                s1 = fmaf(bx, qq.x, s1);
                s1 = fmaf(by, qq.y, s1);
                s1 = fmaf(bz, qq.z, s1);
                if (k == 0) {
                    acc0 = fminf(acc0, s0);    // row1 at k=0 would be self-pair
                } else if (e & 1) {
                    acc1 = fminf(acc1, s0); acc3 = fminf(acc3, s1);
                } else {
                    acc0 = fminf(acc0, s0); acc2 = fminf(acc2, s1);
                }
            }
        }
        {   // k = 32: row1 only
            float s1 = w1 + qt.w;
            s1 = fmaf(bx, qt.x, s1);
            s1 = fmaf(by, qt.y, s1);
            s1 = fmaf(bz, qt.z, s1);
            acc2 = fminf(acc2, s1);
        }
        const float dmin = fminf(fminf(acc0, acc1), fminf(acc2, acc3));

        // rare exact slow path over owned pairs (exact difference arithmetic)
        if (dmin < R2_GUARD) {
            const float4* C = P + r0 + jb;
            for (int k = 0; k <= 32; ++k) {
                const float4 qq = C[k];
                if (k <= 31) {                 // row0 pair, j = jb + k
                    float dx = A.x - qq.x, dy = A.y - qq.y, dz = A.z - qq.z;
                    float e2 = dx * dx + dy * dy + dz * dz;
                    if (e2 < R2) {
                        float c = MIN_DIST - sqrtf(e2);
                        penacc += (jb + k == 64) ? 0.5f * c : c;
                    }
                }
                if (k >= 1) {                  // row1 pair, j = jb + k - 1
                    float dx = Bv.x - qq.x, dy = Bv.y - qq.y, dz = Bv.z - qq.z;
                    float e2 = dx * dx + dy * dy + dz * dz;
                    if (e2 < R2) {
                        float c = MIN_DIST - sqrtf(e2);
                        penacc += (jb + k - 1 == 64) ? 0.5f * c : c;
                    }
                }
            }
        }
    }

    // ========== block reduction of 5 accumulators ==========
    #pragma unroll
    for (int off = 16; off > 0; off >>= 1) {
        penacc  += __shfl_down_sync(0xffffffffu, penacc,  off);
        wrkacc  += __shfl_down_sync(0xffffffffu, wrkacc,  off);
        stabacc += __shfl_down_sync(0xffffffffu, stabacc, off);
        ke0acc  += __shfl_down_sync(0xffffffffu, ke0acc,  off);
        ke1acc  += __shfl_down_sync(0xffffffffu, ke1acc,  off);
    }
    __shared__ float sm[8][5];
    if ((tid & 31) == 0) {
        int w = tid >> 5;
        sm[w][0] = penacc; sm[w][1] = wrkacc; sm[w][2] = stabacc;
        sm[w][3] = ke0acc; sm[w][4] = ke1acc;
    }
    __syncthreads();
    if (tid == 0) {
        float sp = 0.f, sw = 0.f, ss = 0.f, s0v = 0.f, s1v = 0.f;
        #pragma unroll
        for (int w = 0; w < 8; ++w) {
            sp += sm[w][0]; sw += sm[w][1]; ss += sm[w][2];
            s0v += sm[w][3]; s1v += sm[w][4];
        }
        g_pen[blockIdx.x]  = sp;
        g_work[blockIdx.x] = sw;
        g_stab[blockIdx.x] = ss;
        g_ke0[blockIdx.x]  = s0v;
        g_ke1[blockIdx.x]  = s1v;
    }

    // ========== last block: deterministic final reduction ==========
    __threadfence();
    __shared__ int is_last;
    if (tid == 0) {
        unsigned int old = atomicAdd(&g_count, 1u);
        is_last = (old == BLOCKS - 1) ? 1 : 0;
    }
    __syncthreads();
    if (!is_last) return;

    float pen_s = 0.f, wrk_s = 0.f, stab_s = 0.f, k0 = 0.f, k1 = 0.f;
    #pragma unroll
    for (int q = tid; q < BLOCKS; q += 256) {
        pen_s  += g_pen[q];
        wrk_s  += g_work[q];
        stab_s += g_stab[q];
        k0     += g_ke0[q];
        k1     += g_ke1[q];
    }
    #pragma unroll
    for (int off = 16; off > 0; off >>= 1) {
        pen_s  += __shfl_down_sync(0xffffffffu, pen_s,  off);
        wrk_s  += __shfl_down_sync(0xffffffffu, wrk_s,  off);
        stab_s += __shfl_down_sync(0xffffffffu, stab_s, off);
        k0     += __shfl_down_sync(0xffffffffu, k0,     off);
        k1     += __shfl_down_sync(0xffffffffu, k1,     off);
    }
    if ((tid & 31) == 0) {
        int w = tid >> 5;
        sm[w][0] = pen_s; sm[w][1] = wrk_s; sm[w][2] = stab_s;
        sm[w][3] = k0;    sm[w][4] = k1;
    }
    __syncthreads();
    if (tid == 0) {
        float sp = 0.f, sw = 0.f, ss = 0.f, s0v = 0.f, s1v = 0.f;
        #pragma unroll
        for (int w = 0; w < 8; ++w) {
            sp += sm[w][0]; sw += sm[w][1]; ss += sm[w][2];
            s0v += sm[w][3]; s1v += sm[w][4];
        }
        const float pen_loss  = sp / (float)B / ((float)T * (float)N * (float)(N - 1) * 0.5f);
        const float work_mean = sw / (float)(B * (T - 1) * N);
        const float stab_mean = ss / (float)(B * 5 * N);
        const float ks        = s0v / (float)(B * N);
        const float ke_       = s1v / (float)(B * N);
        out[0] = 10.0f * pen_loss + stab_mean + 0.1f * fabsf(ke_ - ks - work_mean);
        g_count = 0u;   // self-reset for next graph replay
    }
}

extern "C" void kernel_launch(void* const* d_in, const int* in_sizes, int n_in,
                              void* d_out, int out_size)
{
    const float* traj = (const float*)d_in[0];
    const float* vel  = (const float*)d_in[1];
    const float* frc  = (const float*)d_in[2];

    fused_kernel<<<BLOCKS, 256>>>(traj, vel, frc, (float*)d_out);
}

// round 12
// speedup vs baseline: 1.1045x; 1.1045x over previous
#include <cuda_runtime.h>
#include <math.h>
#include <stdint.h>

namespace {
constexpr int B = 16, T = 100, N = 128, D = 3;
constexpr int FRAMES = B * T;                 // 1600
constexpr int NIT = 4;                        // frames per block
constexpr int BLOCKS = FRAMES / NIT;          // 400
constexpr int FD = N * D;                     // 384 floats per frame
constexpr int F4 = FD / 4;                    // 96 float4 per frame
constexpr float MIN_DIST = 0.05f;
constexpr float R2 = MIN_DIST * MIN_DIST;     // 0.0025
constexpr float R2_GUARD = R2 + 1e-4f;        // slack for expansion error
}

__device__ float g_pen[BLOCKS];
__device__ float g_work[BLOCKS];
__device__ float g_stab[BLOCKS];
__device__ float g_ke0[BLOCKS];
__device__ float g_ke1[BLOCKS];
__device__ unsigned int g_count;              // zero-init; self-resetting

// tile (I,J) lookup, I <= J; diagonal tiles: tt in {0,4,7,9}
__constant__ int c_tileI[10] = {0, 0, 0, 0, 1, 1, 1, 2, 2, 3};
__constant__ int c_tileJ[10] = {0, 1, 2, 3, 1, 2, 3, 2, 3, 3};

// volatile LDS.128 — pinned program order defeats ptxas load-sinking
__device__ __forceinline__ float4 lds128(uint32_t a) {
    float4 v;
    asm volatile("ld.shared.v4.f32 {%0,%1,%2,%3}, [%4];"
                 : "=f"(v.x), "=f"(v.y), "=f"(v.z), "=f"(v.w) : "r"(a));
    return v;
}

__global__ __launch_bounds__(256) void fused_kernel(
    const float* __restrict__ traj,
    const float* __restrict__ vel,
    const float* __restrict__ frc,
    float* __restrict__ out)
{
    const int tid  = threadIdx.x;
    const int wid  = tid >> 5;
    const int lane = tid & 31;
    const int f0   = blockIdx.x * NIT;
    const int fmod = f0 % T;
    const bool needvel = (fmod == 0) | (fmod == 92) | (fmod == 96);

    __shared__ __align__(16) float4 sP[NIT][N];          // (x,y,z,|p|^2)
    __shared__ __align__(16) float  sT[(NIT + 1) * FD];  // raw traj: 5 frames
    __shared__ __align__(16) float  sF[NIT * FD];        // raw frc: 4 frames
    __shared__ __align__(16) float  sV[NIT * FD];        // raw vel: 4 frames

    // ========== phase 1: single bulk LDG burst (max MLP) ==========
    {
        const float4* t4  = reinterpret_cast<const float4*>(traj);
        const float4* fr4 = reinterpret_cast<const float4*>(frc);
        const float4* v4  = reinterpret_cast<const float4*>(vel);
        float4* dT = reinterpret_cast<float4*>(sT);
        float4* dF = reinterpret_cast<float4*>(sF);
        float4* dV = reinterpret_cast<float4*>(sV);
        const int baseT = f0 * F4;
        const float4 zero = make_float4(0, 0, 0, 0);

        {   // traj: 5 frames = 480 float4 (guard lookahead at global end)
            int idx = tid;
            dT[idx] = (baseT + idx < FRAMES * F4) ? t4[baseT + idx] : zero;
            idx = tid + 256;
            if (idx < (NIT + 1) * F4)
                dT[idx] = (baseT + idx < FRAMES * F4) ? t4[baseT + idx] : zero;
        }
        {   // frc: 4 frames = 384 float4
            dF[tid] = fr4[baseT + tid];
            int idx = tid + 256;
            if (idx < NIT * F4) dF[idx] = fr4[baseT + idx];
        }
        if (needvel) {
            dV[tid] = v4[baseT + tid];
            int idx = tid + 256;
            if (idx < NIT * F4) dV[idx] = v4[baseT + idx];
        }
    }
    __syncthreads();

    // ========== phase 2: build float4 frames (+|p|^2) + cheap terms ==========
    float penacc = 0.f, wrkacc = 0.f, stabacc = 0.f, ke0acc = 0.f, ke1acc = 0.f;
    #pragma unroll
    for (int k = 0; k < 2; ++k) {
        const int s  = tid + 256 * k;          // slot 0..511
        const int fl = s >> 7;                 // local frame 0..3
        const int p  = s & 127;                // point index
        const int t  = (f0 + fl) % T;

        const float x = sT[fl * FD + 3 * p];
        const float y = sT[fl * FD + 3 * p + 1];
        const float z = sT[fl * FD + 3 * p + 2];
        sP[fl][p] = make_float4(x, y, z, x * x + y * y + z * z);

        if (t < T - 1) {                       // work term from staged data
            const float nx = sT[(fl + 1) * FD + 3 * p];
            const float ny = sT[(fl + 1) * FD + 3 * p + 1];
            const float nz = sT[(fl + 1) * FD + 3 * p + 2];
            const float fx = sF[fl * FD + 3 * p];
            const float fy = sF[fl * FD + 3 * p + 1];
            const float fz = sF[fl * FD + 3 * p + 2];
            wrkacc += fx * (nx - x) + fy * (ny - y) + fz * (nz - z);
        }
        if (t == 0 || t >= T - 5) {            // boundary vel terms (smem-staged)
            const float vx = sV[fl * FD + 3 * p];
            const float vy = sV[fl * FD + 3 * p + 1];
            const float vz = sV[fl * FD + 3 * p + 2];
            const float v2 = vx * vx + vy * vy + vz * vz;
            if (t >= T - 5) {
                stabacc += sqrtf(v2);
                if (t == T - 1) ke1acc += 0.5f * v2;
            } else {
                ke0acc += 0.5f * v2;
            }
        }
    }
    __syncthreads();

    // ========== phase 3: 40 warp-tile jobs, broadcast column loads ==========
    #pragma unroll 1
    for (int jj = 0; jj < 5; ++jj) {
        const int job = wid + 8 * jj;          // 0..39
        const int fl  = job / 10;              // frame
        const int tt  = job - 10 * fl;         // tile id
        const int I   = c_tileI[tt];
        const int J   = c_tileJ[tt];
        const bool diag = (I == J);

        const float4* P = sP[fl];
        const float4  A = P[I * 32 + lane];    // this lane's row point
        const float w0 = A.w;
        const float ax = -2.0f * A.x;
        const float ay = -2.0f * A.y;
        const float az = -2.0f * A.z;

        // warp-uniform column base -> broadcast LDS (1 wavefront per load)
        const uint32_t ca =
            (uint32_t)__cvta_generic_to_shared(P + J * 32);

        float4 q0[4], q1[4];
        #pragma unroll
        for (int e = 0; e < 4; ++e) q0[e] = lds128(ca + 16 * e);

        float accA = 1e30f, accB = 1e30f;
        #pragma unroll
        for (int b = 0; b < 8; ++b) {
            if (b < 7) {                       // prefetch next batch
                const uint32_t na = ca + 64 * (b + 1);
                if (b & 1) {
                    #pragma unroll
                    for (int e = 0; e < 4; ++e) q0[e] = lds128(na + 16 * e);
                } else {
                    #pragma unroll
                    for (int e = 0; e < 4; ++e) q1[e] = lds128(na + 16 * e);
                }
            }
            #pragma unroll
            for (int e = 0; e < 4; ++e) {
                const int k = 4 * b + e;
                const float4 qq = (b & 1) ? q1[e] : q0[e];
                float s = w0 + qq.w;
                s = fmaf(ax, qq.x, s);
                s = fmaf(ay, qq.y, s);
                s = fmaf(az, qq.z, s);
                if (diag && k <= lane) s = 1e30f;   // mask self/lower half
                if (e & 1) accB = fminf(accB, s);
                else       accA = fminf(accA, s);
            }
        }

        // rare exact slow path over this tile's owned pairs
        if (fminf(accA, accB) < R2_GUARD) {
            const float4* C = P + J * 32;
            for (int k = 0; k < 32; ++k) {
                if (diag && k <= lane) continue;
                const float4 qq = C[k];
                float dx = A.x - qq.x, dy = A.y - qq.y, dz = A.z - qq.z;
                float e2 = dx * dx + dy * dy + dz * dz;
                if (e2 < R2) penacc += MIN_DIST - sqrtf(e2);
            }
        }
    }

    // ========== block reduction of 5 accumulators ==========
    #pragma unroll
    for (int off = 16; off > 0; off >>= 1) {
        penacc  += __shfl_down_sync(0xffffffffu, penacc,  off);
        wrkacc  += __shfl_down_sync(0xffffffffu, wrkacc,  off);
        stabacc += __shfl_down_sync(0xffffffffu, stabacc, off);
        ke0acc  += __shfl_down_sync(0xffffffffu, ke0acc,  off);
        ke1acc  += __shfl_down_sync(0xffffffffu, ke1acc,  off);
    }
    __shared__ float sm[8][5];
    if (lane == 0) {
        sm[wid][0] = penacc; sm[wid][1] = wrkacc; sm[wid][2] = stabacc;
        sm[wid][3] = ke0acc; sm[wid][4] = ke1acc;
    }
    __syncthreads();
    if (tid == 0) {
        float sp = 0.f, sw = 0.f, ss = 0.f, s0v = 0.f, s1v = 0.f;
        #pragma unroll
        for (int w = 0; w < 8; ++w) {
            sp += sm[w][0]; sw += sm[w][1]; ss += sm[w][2];
            s0v += sm[w][3]; s1v += sm[w][4];
        }
        g_pen[blockIdx.x]  = sp;
        g_work[blockIdx.x] = sw;
        g_stab[blockIdx.x] = ss;
        g_ke0[blockIdx.x]  = s0v;
        g_ke1[blockIdx.x]  = s1v;
    }

    // ========== last block: deterministic final reduction ==========
    __threadfence();
    __shared__ int is_last;
    if (tid == 0) {
        unsigned int old = atomicAdd(&g_count, 1u);
        is_last = (old == BLOCKS - 1) ? 1 : 0;
    }
    __syncthreads();
    if (!is_last) return;

    float pen_s = 0.f, wrk_s = 0.f, stab_s = 0.f, k0 = 0.f, k1 = 0.f;
    #pragma unroll
    for (int q = tid; q < BLOCKS; q += 256) {
        pen_s  += g_pen[q];
        wrk_s  += g_work[q];
        stab_s += g_stab[q];
        k0     += g_ke0[q];
        k1     += g_ke1[q];
    }
    #pragma unroll
    for (int off = 16; off > 0; off >>= 1) {
        pen_s  += __shfl_down_sync(0xffffffffu, pen_s,  off);
        wrk_s  += __shfl_down_sync(0xffffffffu, wrk_s,  off);
        stab_s += __shfl_down_sync(0xffffffffu, stab_s, off);
        k0     += __shfl_down_sync(0xffffffffu, k0,     off);
        k1     += __shfl_down_sync(0xffffffffu, k1,     off);
    }
    if (lane == 0) {
        sm[wid][0] = pen_s; sm[wid][1] = wrk_s; sm[wid][2] = stab_s;
        sm[wid][3] = k0;    sm[wid][4] = k1;
    }
    __syncthreads();
    if (tid == 0) {
        float sp = 0.f, sw = 0.f, ss = 0.f, s0v = 0.f, s1v = 0.f;
        #pragma unroll
        for (int w = 0; w < 8; ++w) {
            sp += sm[w][0]; sw += sm[w][1]; ss += sm[w][2];
            s0v += sm[w][3]; s1v += sm[w][4];
        }
        const float pen_loss  = sp / (float)B / ((float)T * (float)N * (float)(N - 1) * 0.5f);
        const float work_mean = sw / (float)(B * (T - 1) * N);
        const float stab_mean = ss / (float)(B * 5 * N);
        const float ks        = s0v / (float)(B * N);
        const float ke_       = s1v / (float)(B * N);
        out[0] = 10.0f * pen_loss + stab_mean + 0.1f * fabsf(ke_ - ks - work_mean);
        g_count = 0u;   // self-reset for next graph replay
    }
}

extern "C" void kernel_launch(void* const* d_in, const int* in_sizes, int n_in,
                              void* d_out, int out_size)
{
    const float* traj = (const float*)d_in[0];
    const float* vel  = (const float*)d_in[1];
    const float* frc  = (const float*)d_in[2];

    fused_kernel<<<BLOCKS, 256>>>(traj, vel, frc, (float*)d_out);
}

// round 13
// speedup vs baseline: 1.1065x; 1.0019x over previous
#include <cuda_runtime.h>
#include <math.h>
#include <stdint.h>

typedef unsigned long long ull;

namespace {
constexpr int B = 16, T = 100, N = 128, D = 3;
constexpr int FRAMES = B * T;                 // 1600
constexpr int NIT = 4;                        // frames per block
constexpr int BLOCKS = FRAMES / NIT;          // 400
constexpr int FD = N * D;                     // 384 floats per frame
constexpr int F4 = FD / 4;                    // 96 float4 per frame
constexpr float MIN_DIST = 0.05f;
constexpr float R2 = MIN_DIST * MIN_DIST;     // 0.0025
constexpr float R2_GUARD = R2 + 1e-4f;        // slack for expansion error
}

__device__ float g_pen[BLOCKS];
__device__ float g_work[BLOCKS];
__device__ float g_stab[BLOCKS];
__device__ float g_ke0[BLOCKS];
__device__ float g_ke1[BLOCKS];
__device__ unsigned int g_count;              // zero-init; self-resetting

// job -> (frame, tileI, tileJ); 40 jobs = 4 frames x 10 tiles
__constant__ unsigned char c_fl[40] = {
    0,0,0,0,0,0,0,0,0,0, 1,1,1,1,1,1,1,1,1,1,
    2,2,2,2,2,2,2,2,2,2, 3,3,3,3,3,3,3,3,3,3};
__constant__ unsigned char c_I[40] = {
    0,0,0,0,1,1,1,2,2,3, 0,0,0,0,1,1,1,2,2,3,
    0,0,0,0,1,1,1,2,2,3, 0,0,0,0,1,1,1,2,2,3};
__constant__ unsigned char c_J[40] = {
    0,1,2,3,1,2,3,2,3,3, 0,1,2,3,1,2,3,2,3,3,
    0,1,2,3,1,2,3,2,3,3, 0,1,2,3,1,2,3,2,3,3};

// ---- packed f32x2 helpers ----
__device__ __forceinline__ ull pk2(float v) {
    ull r; asm("mov.b64 %0, {%1,%1};" : "=l"(r) : "f"(v)); return r;
}
__device__ __forceinline__ void upk(ull v, uint32_t& lo, uint32_t& hi) {
    asm("mov.b64 {%0,%1}, %2;" : "=r"(lo), "=r"(hi) : "l"(v));
}
__device__ __forceinline__ ull f2add(ull a, ull b) {
    ull r; asm("add.rn.f32x2 %0, %1, %2;" : "=l"(r) : "l"(a), "l"(b)); return r;
}
__device__ __forceinline__ ull f2fma(ull a, ull b, ull c) {
    ull r; asm("fma.rn.f32x2 %0, %1, %2, %3;" : "=l"(r) : "l"(a), "l"(b), "l"(c)); return r;
}
// volatile LDS.128 as two packed u64 (pre-packed f32x2 operands)
__device__ __forceinline__ void ldsp(uint32_t a, ull& p0, ull& p1) {
    asm volatile("ld.shared.v2.u64 {%0,%1}, [%2];" : "=l"(p0), "=l"(p1) : "r"(a));
}

__global__ __launch_bounds__(256) void fused_kernel(
    const float* __restrict__ traj,
    const float* __restrict__ vel,
    const float* __restrict__ frc,
    float* __restrict__ out)
{
    const int tid  = threadIdx.x;
    const int wid  = tid >> 5;
    const int lane = tid & 31;
    const int f0   = blockIdx.x * NIT;
    const int fmod = f0 % T;
    const bool needvel = (fmod == 0) | (fmod == 92) | (fmod == 96);

    // paired SoA: slot k2 of sXY = {x(2k2), x(2k2+1), y(2k2), y(2k2+1)}
    //             slot k2 of sZW = {z(2k2), z(2k2+1), w(2k2), w(2k2+1)}
    __shared__ __align__(16) float4 sXY[NIT][64];
    __shared__ __align__(16) float4 sZW[NIT][64];
    __shared__ __align__(16) float  sT[(NIT + 1) * FD];  // raw traj: 5 frames
    __shared__ __align__(16) float  sF[NIT * FD];        // raw frc: 4 frames
    __shared__ __align__(16) float  sV[NIT * FD];        // raw vel: 4 frames

    // ========== phase 1: single bulk LDG burst (max MLP) ==========
    {
        const float4* t4  = reinterpret_cast<const float4*>(traj);
        const float4* fr4 = reinterpret_cast<const float4*>(frc);
        const float4* v4  = reinterpret_cast<const float4*>(vel);
        float4* dT = reinterpret_cast<float4*>(sT);
        float4* dF = reinterpret_cast<float4*>(sF);
        float4* dV = reinterpret_cast<float4*>(sV);
        const int baseT = f0 * F4;
        const float4 zero = make_float4(0, 0, 0, 0);

        {   // traj: 5 frames = 480 float4 (guard lookahead at global end)
            int idx = tid;
            dT[idx] = (baseT + idx < FRAMES * F4) ? t4[baseT + idx] : zero;
            idx = tid + 256;
            if (idx < (NIT + 1) * F4)
                dT[idx] = (baseT + idx < FRAMES * F4) ? t4[baseT + idx] : zero;
        }
        {   // frc: 4 frames = 384 float4
            dF[tid] = fr4[baseT + tid];
            int idx = tid + 256;
            if (idx < NIT * F4) dF[idx] = fr4[baseT + idx];
        }
        if (needvel) {
            dV[tid] = v4[baseT + tid];
            int idx = tid + 256;
            if (idx < NIT * F4) dV[idx] = v4[baseT + idx];
        }
    }
    __syncthreads();

    // ========== phase 2: build paired SoA frames + cheap terms ==========
    float penacc = 0.f, wrkacc = 0.f, stabacc = 0.f, ke0acc = 0.f, ke1acc = 0.f;
    #pragma unroll
    for (int k = 0; k < 2; ++k) {
        const int s  = tid + 256 * k;          // slot 0..511
        const int fl = s >> 7;                 // local frame 0..3
        const int p  = s & 127;                // point index
        const int t  = (f0 + fl) % T;

        const float x = sT[fl * FD + 3 * p];
        const float y = sT[fl * FD + 3 * p + 1];
        const float z = sT[fl * FD + 3 * p + 2];
        const float w = x * x + y * y + z * z;
        {
            float* bXY = reinterpret_cast<float*>(sXY[fl]);
            float* bZW = reinterpret_cast<float*>(sZW[fl]);
            const int k2 = p >> 1, hl = p & 1;
            bXY[4 * k2 + hl]     = x;
            bXY[4 * k2 + 2 + hl] = y;
            bZW[4 * k2 + hl]     = z;
            bZW[4 * k2 + 2 + hl] = w;
        }

        if (t < T - 1) {                       // work term from staged data
            const float nx = sT[(fl + 1) * FD + 3 * p];
            const float ny = sT[(fl + 1) * FD + 3 * p + 1];
            const float nz = sT[(fl + 1) * FD + 3 * p + 2];
            const float fx = sF[fl * FD + 3 * p];
            const float fy = sF[fl * FD + 3 * p + 1];
            const float fz = sF[fl * FD + 3 * p + 2];
            wrkacc += fx * (nx - x) + fy * (ny - y) + fz * (nz - z);
        }
        if (t == 0 || t >= T - 5) {            // boundary vel terms (smem-staged)
            const float vx = sV[fl * FD + 3 * p];
            const float vy = sV[fl * FD + 3 * p + 1];
            const float vz = sV[fl * FD + 3 * p + 2];
            const float v2 = vx * vx + vy * vy + vz * vz;
            if (t >= T - 5) {
                stabacc += sqrtf(v2);
                if (t == T - 1) ke1acc += 0.5f * v2;
            } else {
                ke0acc += 0.5f * v2;
            }
        }
    }
    __syncthreads();

    // ========== phase 3: 40 warp-tile jobs, packed math + sign detection ====
    #pragma unroll 1
    for (int jj = 0; jj < 5; ++jj) {
        const int job = wid + 8 * jj;          // 0..39
        const int fl  = c_fl[job];
        const int I   = c_I[job];
        const int J   = c_J[job];
        const bool diag = (I == J);

        // row point of this lane (tile I, row = lane)
        const float* bXY = reinterpret_cast<const float*>(sXY[fl] + I * 16);
        const float* bZW = reinterpret_cast<const float*>(sZW[fl] + I * 16);
        const int k2s = lane >> 1, hls = lane & 1;
        const float Axv = bXY[4 * k2s + hls];
        const float Ayv = bXY[4 * k2s + 2 + hls];
        const float Azv = bZW[4 * k2s + hls];
        const float Awv = bZW[4 * k2s + 2 + hls];
        const ull axp = pk2(-2.0f * Axv);
        const ull ayp = pk2(-2.0f * Ayv);
        const ull azp = pk2(-2.0f * Azv);
        const ull w0g = pk2(Awv - R2_GUARD);

        // warp-uniform column bases -> broadcast LDS
        const uint32_t caXY =
            (uint32_t)__cvta_generic_to_shared(sXY[fl] + J * 16);
        const uint32_t caZW =
            (uint32_t)__cvta_generic_to_shared(sZW[fl] + J * 16);

        // double-buffered batches of 2 slots (= 4 columns)
        ull x0[2], y0[2], z0[2], w0[2], x1[2], y1[2], z1[2], w1[2];
        ldsp(caXY,      x0[0], y0[0]);
        ldsp(caZW,      z0[0], w0[0]);
        ldsp(caXY + 16, x0[1], y0[1]);
        ldsp(caZW + 16, z0[1], w0[1]);

        uint32_t detu = 0, cnt = 0;
        #pragma unroll
        for (int b = 0; b < 8; ++b) {          // 8 batches x 2 slots
            if (b < 7) {                       // prefetch next batch
                const uint32_t off = 32 * (b + 1);
                if (b & 1) {
                    ldsp(caXY + off,      x0[0], y0[0]);
                    ldsp(caZW + off,      z0[0], w0[0]);
                    ldsp(caXY + off + 16, x0[1], y0[1]);
                    ldsp(caZW + off + 16, z0[1], w0[1]);
                } else {
                    ldsp(caXY + off,      x1[0], y1[0]);
                    ldsp(caZW + off,      z1[0], w1[0]);
                    ldsp(caXY + off + 16, x1[1], y1[1]);
                    ldsp(caZW + off + 16, z1[1], w1[1]);
                }
            }
            #pragma unroll
            for (int e = 0; e < 2; ++e) {
                const ull xp = (b & 1) ? x1[e] : x0[e];
                const ull yp = (b & 1) ? y1[e] : y0[e];
                const ull zp = (b & 1) ? z1[e] : z0[e];
                const ull wp = (b & 1) ? w1[e] : w0[e];
                ull s = f2add(w0g, wp);
                s = f2fma(axp, xp, s);
                s = f2fma(ayp, yp, s);
                s = f2fma(azp, zp, s);
                uint32_t lo, hi; upk(s, lo, hi);
                if (diag) cnt += (lo >> 31) + (hi >> 31);  // self always fires
                else      detu |= lo | hi;
            }
        }

        const bool trigger = diag ? (cnt >= 2u) : ((detu >> 31) != 0u);

        // rare exact slow path over this tile's owned pairs
        if (trigger) {
            const float* cXY = reinterpret_cast<const float*>(sXY[fl] + J * 16);
            const float* cZW = reinterpret_cast<const float*>(sZW[fl] + J * 16);
            for (int c = 0; c < 32; ++c) {
                if (diag && c <= lane) continue;
                const int ck = c >> 1, ch = c & 1;
                const float qx = cXY[4 * ck + ch];
                const float qy = cXY[4 * ck + 2 + ch];
                const float qz = cZW[4 * ck + ch];
                float dx = Axv - qx, dy = Ayv - qy, dz = Azv - qz;
                float e2 = dx * dx + dy * dy + dz * dz;
                if (e2 < R2) penacc += MIN_DIST - sqrtf(e2);
            }
        }
    }

    // ========== block reduction of 5 accumulators ==========
    #pragma unroll
    for (int off = 16; off > 0; off >>= 1) {
        penacc  += __shfl_down_sync(0xffffffffu, penacc,  off);
        wrkacc  += __shfl_down_sync(0xffffffffu, wrkacc,  off);
        stabacc += __shfl_down_sync(0xffffffffu, stabacc, off);
        ke0acc  += __shfl_down_sync(0xffffffffu, ke0acc,  off);
        ke1acc  += __shfl_down_sync(0xffffffffu, ke1acc,  off);
    }
    __shared__ float sm[8][5];
    if (lane == 0) {
        sm[wid][0] = penacc; sm[wid][1] = wrkacc; sm[wid][2] = stabacc;
        sm[wid][3] = ke0acc; sm[wid][4] = ke1acc;
    }
    __syncthreads();
    if (tid == 0) {
        float sp = 0.f, sw = 0.f, ss = 0.f, s0v = 0.f, s1v = 0.f;
        #pragma unroll
        for (int w = 0; w < 8; ++w) {
            sp += sm[w][0]; sw += sm[w][1]; ss += sm[w][2];
            s0v += sm[w][3]; s1v += sm[w][4];
        }
        g_pen[blockIdx.x]  = sp;
        g_work[blockIdx.x] = sw;
        g_stab[blockIdx.x] = ss;
        g_ke0[blockIdx.x]  = s0v;
        g_ke1[blockIdx.x]  = s1v;
    }

    // ========== last block: deterministic final reduction ==========
    __threadfence();
    __shared__ int is_last;
    if (tid == 0) {
        unsigned int old = atomicAdd(&g_count, 1u);
        is_last = (old == BLOCKS - 1) ? 1 : 0;
    }
    __syncthreads();
    if (!is_last) return;

    float pen_s = 0.f, wrk_s = 0.f, stab_s = 0.f, k0 = 0.f, k1 = 0.f;
    #pragma unroll
    for (int q = tid; q < BLOCKS; q += 256) {
        pen_s  += g_pen[q];
        wrk_s  += g_work[q];
        stab_s += g_stab[q];
        k0     += g_ke0[q];
        k1     += g_ke1[q];
    }
    #pragma unroll
    for (int off = 16; off > 0; off >>= 1) {
        pen_s  += __shfl_down_sync(0xffffffffu, pen_s,  off);
        wrk_s  += __shfl_down_sync(0xffffffffu, wrk_s,  off);
        stab_s += __shfl_down_sync(0xffffffffu, stab_s, off);
        k0     += __shfl_down_sync(0xffffffffu, k0,     off);
        k1     += __shfl_down_sync(0xffffffffu, k1,     off);
    }
    if (lane == 0) {
        sm[wid][0] = pen_s; sm[wid][1] = wrk_s; sm[wid][2] = stab_s;
        sm[wid][3] = k0;    sm[wid][4] = k1;
    }
    __syncthreads();
    if (tid == 0) {
        float sp = 0.f, sw = 0.f, ss = 0.f, s0v = 0.f, s1v = 0.f;
        #pragma unroll
        for (int w = 0; w < 8; ++w) {
            sp += sm[w][0]; sw += sm[w][1]; ss += sm[w][2];
            s0v += sm[w][3]; s1v += sm[w][4];
        }
        const float pen_loss  = sp / (float)B / ((float)T * (float)N * (float)(N - 1) * 0.5f);
        const float work_mean = sw / (float)(B * (T - 1) * N);
        const float stab_mean = ss / (float)(B * 5 * N);
        const float ks        = s0v / (float)(B * N);
        const float ke_       = s1v / (float)(B * N);
        out[0] = 10.0f * pen_loss + stab_mean + 0.1f * fabsf(ke_ - ks - work_mean);
        g_count = 0u;   // self-reset for next graph replay
    }
}

extern "C" void kernel_launch(void* const* d_in, const int* in_sizes, int n_in,
                              void* d_out, int out_size)
{
    const float* traj = (const float*)d_in[0];
    const float* vel  = (const float*)d_in[1];
    const float* frc  = (const float*)d_in[2];

    fused_kernel<<<BLOCKS, 256>>>(traj, vel, frc, (float*)d_out);
}

// round 14
// speedup vs baseline: 1.2759x; 1.1530x over previous
#include <cuda_runtime.h>
#include <math.h>
#include <stdint.h>

typedef unsigned long long ull;

namespace {
constexpr int B = 16, T = 100, N = 128, D = 3;
constexpr int FRAMES = B * T;                 // 1600
constexpr int NIT = 4;                        // frames per block
constexpr int BLOCKS = FRAMES / NIT;          // 400
constexpr int THREADS = 512;
constexpr int FD = N * D;                     // 384 floats per frame
constexpr int F4 = FD / 4;                    // 96 float4 per frame
constexpr float MIN_DIST = 0.05f;
constexpr float R2 = MIN_DIST * MIN_DIST;     // 0.0025
constexpr float R2_GUARD = R2 + 1e-4f;        // slack for expansion error
}

__device__ float g_pen[BLOCKS];
__device__ float g_work[BLOCKS];
__device__ float g_stab[BLOCKS];
__device__ float g_ke0[BLOCKS];
__device__ float g_ke1[BLOCKS];
__device__ unsigned int g_count;              // zero-init; self-resetting

// 80 half-jobs: job -> (frame fl, tile row I, tile col J, col-half ch)
// tiles (I,J), I<=J: (0,0)(0,1)(0,2)(0,3)(1,1)(1,2)(1,3)(2,2)(2,3)(3,3)
#define TILE_I0 0,0,0,0,0,0,0,0,1,1,1,1,1,1,2,2,2,2,3,3
#define TILE_J0 0,0,1,1,2,2,3,3,1,1,2,2,3,3,2,2,3,3,3,3
#define TILE_C0 0,1,0,1,0,1,0,1,0,1,0,1,0,1,0,1,0,1,0,1
__constant__ unsigned char c_fl[80] = {
    0,0,0,0,0,0,0,0,0,0,0,0,0,0,0,0,0,0,0,0,
    1,1,1,1,1,1,1,1,1,1,1,1,1,1,1,1,1,1,1,1,
    2,2,2,2,2,2,2,2,2,2,2,2,2,2,2,2,2,2,2,2,
    3,3,3,3,3,3,3,3,3,3,3,3,3,3,3,3,3,3,3,3};
__constant__ unsigned char c_I[80] = {TILE_I0, TILE_I0, TILE_I0, TILE_I0};
__constant__ unsigned char c_J[80] = {TILE_J0, TILE_J0, TILE_J0, TILE_J0};
__constant__ unsigned char c_C[80] = {TILE_C0, TILE_C0, TILE_C0, TILE_C0};

// ---- packed f32x2 helpers ----
__device__ __forceinline__ ull pk2(float v) {
    ull r; asm("mov.b64 %0, {%1,%1};" : "=l"(r) : "f"(v)); return r;
}
__device__ __forceinline__ void upk(ull v, uint32_t& lo, uint32_t& hi) {
    asm("mov.b64 {%0,%1}, %2;" : "=r"(lo), "=r"(hi) : "l"(v));
}
__device__ __forceinline__ ull f2add(ull a, ull b) {
    ull r; asm("add.rn.f32x2 %0, %1, %2;" : "=l"(r) : "l"(a), "l"(b)); return r;
}
__device__ __forceinline__ ull f2fma(ull a, ull b, ull c) {
    ull r; asm("fma.rn.f32x2 %0, %1, %2, %3;" : "=l"(r) : "l"(a), "l"(b), "l"(c)); return r;
}
// volatile LDS.128 as two packed u64 (pre-packed f32x2 operands)
__device__ __forceinline__ void ldsp(uint32_t a, ull& p0, ull& p1) {
    asm volatile("ld.shared.v2.u64 {%0,%1}, [%2];" : "=l"(p0), "=l"(p1) : "r"(a));
}

__global__ __launch_bounds__(THREADS) void fused_kernel(
    const float* __restrict__ traj,
    const float* __restrict__ vel,
    const float* __restrict__ frc,
    float* __restrict__ out)
{
    const int tid  = threadIdx.x;
    const int wid  = tid >> 5;                 // 0..15
    const int lane = tid & 31;
    const int f0   = blockIdx.x * NIT;
    const int fmod = f0 % T;
    const bool needvel = (fmod == 0) | (fmod == 92) | (fmod == 96);

    // paired SoA: slot k2 of sXY = {x(2k2), x(2k2+1), y(2k2), y(2k2+1)}
    //             slot k2 of sZW = {z(2k2), z(2k2+1), w(2k2), w(2k2+1)}
    __shared__ __align__(16) float4 sXY[NIT][64];
    __shared__ __align__(16) float4 sZW[NIT][64];
    __shared__ __align__(16) float  sT[(NIT + 1) * FD];  // raw traj: 5 frames
    __shared__ __align__(16) float  sF[NIT * FD];        // raw frc: 4 frames
    __shared__ __align__(16) float  sV[NIT * FD];        // raw vel: 4 frames

    // ========== phase 1: single bulk LDG burst (max MLP) ==========
    {
        const float4* t4  = reinterpret_cast<const float4*>(traj);
        const float4* fr4 = reinterpret_cast<const float4*>(frc);
        const float4* v4  = reinterpret_cast<const float4*>(vel);
        float4* dT = reinterpret_cast<float4*>(sT);
        float4* dF = reinterpret_cast<float4*>(sF);
        float4* dV = reinterpret_cast<float4*>(sV);
        const int baseT = f0 * F4;
        const float4 zero = make_float4(0, 0, 0, 0);

        if (tid < (NIT + 1) * F4)    // traj: 480 float4 (guard global end)
            dT[tid] = (baseT + tid < FRAMES * F4) ? t4[baseT + tid] : zero;
        if (tid < NIT * F4)          // frc: 384 float4
            dF[tid] = fr4[baseT + tid];
        if (needvel && tid < NIT * F4)
            dV[tid] = v4[baseT + tid];
    }
    __syncthreads();

    // ========== phase 2: single-pass build + cheap terms ==========
    float penacc = 0.f, wrkacc = 0.f, stabacc = 0.f, ke0acc = 0.f, ke1acc = 0.f;
    {
        const int fl = tid >> 7;               // local frame 0..3
        const int p  = tid & 127;              // point index
        const int t  = (f0 + fl) % T;

        const float x = sT[fl * FD + 3 * p];
        const float y = sT[fl * FD + 3 * p + 1];
        const float z = sT[fl * FD + 3 * p + 2];
        const float w = x * x + y * y + z * z;
        {
            float* bXY = reinterpret_cast<float*>(sXY[fl]);
            float* bZW = reinterpret_cast<float*>(sZW[fl]);
            const int k2 = p >> 1, hl = p & 1;
            bXY[4 * k2 + hl]     = x;
            bXY[4 * k2 + 2 + hl] = y;
            bZW[4 * k2 + hl]     = z;
            bZW[4 * k2 + 2 + hl] = w;
        }

        if (t < T - 1) {                       // work term from staged data
            const float nx = sT[(fl + 1) * FD + 3 * p];
            const float ny = sT[(fl + 1) * FD + 3 * p + 1];
            const float nz = sT[(fl + 1) * FD + 3 * p + 2];
            const float fx = sF[fl * FD + 3 * p];
            const float fy = sF[fl * FD + 3 * p + 1];
            const float fz = sF[fl * FD + 3 * p + 2];
            wrkacc = fx * (nx - x) + fy * (ny - y) + fz * (nz - z);
        }
        if (t == 0 || t >= T - 5) {            // boundary vel terms (smem-staged)
            const float vx = sV[fl * FD + 3 * p];
            const float vy = sV[fl * FD + 3 * p + 1];
            const float vz = sV[fl * FD + 3 * p + 2];
            const float v2 = vx * vx + vy * vy + vz * vz;
            if (t >= T - 5) {
                stabacc = sqrtf(v2);
                if (t == T - 1) ke1acc = 0.5f * v2;
            } else {
                ke0acc = 0.5f * v2;
            }
        }
    }
    __syncthreads();

    // ========== phase 3: 80 half-tile jobs, 5 per warp ==========
    #pragma unroll 1
    for (int jj = 0; jj < 5; ++jj) {
        const int job = wid + 16 * jj;         // 0..79
        const int fl  = c_fl[job];
        const int I   = c_I[job];
        const int J   = c_J[job];
        const int ch  = c_C[job];              // column half 0/1
        const bool diag = (I == J);

        // row point of this lane (tile I, row = lane)
        const float* bXY = reinterpret_cast<const float*>(sXY[fl] + I * 16);
        const float* bZW = reinterpret_cast<const float*>(sZW[fl] + I * 16);
        const int k2s = lane >> 1, hls = lane & 1;
        const float Axv = bXY[4 * k2s + hls];
        const float Ayv = bXY[4 * k2s + 2 + hls];
        const float Azv = bZW[4 * k2s + hls];
        const float Awv = bZW[4 * k2s + 2 + hls];
        const ull axp = pk2(-2.0f * Axv);
        const ull ayp = pk2(-2.0f * Ayv);
        const ull azp = pk2(-2.0f * Azv);
        const ull w0g = pk2(Awv - R2_GUARD);

        // warp-uniform column bases (16 columns = 8 paired slots) -> broadcast
        const uint32_t caXY =
            (uint32_t)__cvta_generic_to_shared(sXY[fl] + J * 16 + ch * 8);
        const uint32_t caZW =
            (uint32_t)__cvta_generic_to_shared(sZW[fl] + J * 16 + ch * 8);

        // double-buffered batches of 2 slots (= 4 columns), 4 batches
        ull x0[2], y0[2], z0[2], w0[2], x1[2], y1[2], z1[2], w1[2];
        ldsp(caXY,      x0[0], y0[0]);
        ldsp(caZW,      z0[0], w0[0]);
        ldsp(caXY + 16, x0[1], y0[1]);
        ldsp(caZW + 16, z0[1], w0[1]);

        uint32_t detu = 0, cnt = 0;
        #pragma unroll
        for (int b = 0; b < 4; ++b) {          // 4 batches x 2 slots
            if (b < 3) {                       // prefetch next batch
                const uint32_t off = 32 * (b + 1);
                if (b & 1) {
                    ldsp(caXY + off,      x0[0], y0[0]);
                    ldsp(caZW + off,      z0[0], w0[0]);
                    ldsp(caXY + off + 16, x0[1], y0[1]);
                    ldsp(caZW + off + 16, z0[1], w0[1]);
                } else {
                    ldsp(caXY + off,      x1[0], y1[0]);
                    ldsp(caZW + off,      z1[0], w1[0]);
                    ldsp(caXY + off + 16, x1[1], y1[1]);
                    ldsp(caZW + off + 16, z1[1], w1[1]);
                }
            }
            #pragma unroll
            for (int e = 0; e < 2; ++e) {
                const ull xp = (b & 1) ? x1[e] : x0[e];
                const ull yp = (b & 1) ? y1[e] : y0[e];
                const ull zp = (b & 1) ? z1[e] : z0[e];
                const ull wp = (b & 1) ? w1[e] : w0[e];
                ull s = f2add(w0g, wp);
                s = f2fma(axp, xp, s);
                s = f2fma(ayp, yp, s);
                s = f2fma(azp, zp, s);
                uint32_t lo, hi; upk(s, lo, hi);
                if (diag) cnt += (lo >> 31) + (hi >> 31);
                else      detu |= lo | hi;
            }
        }

        // diag: self-pair fires iff lane lies in this column half
        const bool selfin = diag && ((lane >> 4) == ch);
        const bool trigger = diag ? (cnt > (selfin ? 1u : 0u))
                                  : ((detu >> 31) != 0u);

        // rare exact slow path over this half-tile's owned pairs
        if (trigger) {
            const float* cXY = reinterpret_cast<const float*>(sXY[fl] + J * 16);
            const float* cZW = reinterpret_cast<const float*>(sZW[fl] + J * 16);
            for (int c = 0; c < 16; ++c) {
                const int k = ch * 16 + c;     // column within tile
                if (diag && k <= lane) continue;
                const int ck = k >> 1, chh = k & 1;
                const float qx = cXY[4 * ck + chh];
                const float qy = cXY[4 * ck + 2 + chh];
                const float qz = cZW[4 * ck + chh];
                float dx = Axv - qx, dy = Ayv - qy, dz = Azv - qz;
                float e2 = dx * dx + dy * dy + dz * dz;
                if (e2 < R2) penacc += MIN_DIST - sqrtf(e2);
            }
        }
    }

    // ========== block reduction of 5 accumulators ==========
    #pragma unroll
    for (int off = 16; off > 0; off >>= 1) {
        penacc  += __shfl_down_sync(0xffffffffu, penacc,  off);
        wrkacc  += __shfl_down_sync(0xffffffffu, wrkacc,  off);
        stabacc += __shfl_down_sync(0xffffffffu, stabacc, off);
        ke0acc  += __shfl_down_sync(0xffffffffu, ke0acc,  off);
        ke1acc  += __shfl_down_sync(0xffffffffu, ke1acc,  off);
    }
    __shared__ float sm[16][5];
    if (lane == 0) {
        sm[wid][0] = penacc; sm[wid][1] = wrkacc; sm[wid][2] = stabacc;
        sm[wid][3] = ke0acc; sm[wid][4] = ke1acc;
    }
    __syncthreads();
    if (tid == 0) {
        float sp = 0.f, sw = 0.f, ss = 0.f, s0v = 0.f, s1v = 0.f;
        #pragma unroll
        for (int w = 0; w < 16; ++w) {
            sp += sm[w][0]; sw += sm[w][1]; ss += sm[w][2];
            s0v += sm[w][3]; s1v += sm[w][4];
        }
        g_pen[blockIdx.x]  = sp;
        g_work[blockIdx.x] = sw;
        g_stab[blockIdx.x] = ss;
        g_ke0[blockIdx.x]  = s0v;
        g_ke1[blockIdx.x]  = s1v;
    }

    // ========== last block: deterministic final reduction ==========
    __threadfence();
    __shared__ int is_last;
    if (tid == 0) {
        unsigned int old = atomicAdd(&g_count, 1u);
        is_last = (old == BLOCKS - 1) ? 1 : 0;
    }
    __syncthreads();
    if (!is_last) return;

    float pen_s = 0.f, wrk_s = 0.f, stab_s = 0.f, k0 = 0.f, k1 = 0.f;
    if (tid < BLOCKS) {
        pen_s  = g_pen[tid];
        wrk_s  = g_work[tid];
        stab_s = g_stab[tid];
        k0     = g_ke0[tid];
        k1     = g_ke1[tid];
    }
    #pragma unroll
    for (int off = 16; off > 0; off >>= 1) {
        pen_s  += __shfl_down_sync(0xffffffffu, pen_s,  off);
        wrk_s  += __shfl_down_sync(0xffffffffu, wrk_s,  off);
        stab_s += __shfl_down_sync(0xffffffffu, stab_s, off);
        k0     += __shfl_down_sync(0xffffffffu, k0,     off);
        k1     += __shfl_down_sync(0xffffffffu, k1,     off);
    }
    if (lane == 0) {
        sm[wid][0] = pen_s; sm[wid][1] = wrk_s; sm[wid][2] = stab_s;
        sm[wid][3] = k0;    sm[wid][4] = k1;
    }
    __syncthreads();
    if (tid == 0) {
        float sp = 0.f, sw = 0.f, ss = 0.f, s0v = 0.f, s1v = 0.f;
        #pragma unroll
        for (int w = 0; w < 16; ++w) {
            sp += sm[w][0]; sw += sm[w][1]; ss += sm[w][2];
            s0v += sm[w][3]; s1v += sm[w][4];
        }
        const float pen_loss  = sp / (float)B / ((float)T * (float)N * (float)(N - 1) * 0.5f);
        const float work_mean = sw / (float)(B * (T - 1) * N);
        const float stab_mean = ss / (float)(B * 5 * N);
        const float ks        = s0v / (float)(B * N);
        const float ke_       = s1v / (float)(B * N);
        out[0] = 10.0f * pen_loss + stab_mean + 0.1f * fabsf(ke_ - ks - work_mean);
        g_count = 0u;   // self-reset for next graph replay
    }
}

extern "C" void kernel_launch(void* const* d_in, const int* in_sizes, int n_in,
                              void* d_out, int out_size)
{
    const float* traj = (const float*)d_in[0];
    const float* vel  = (const float*)d_in[1];
    const float* frc  = (const float*)d_in[2];

    fused_kernel<<<BLOCKS, THREADS>>>(traj, vel, frc, (float*)d_out);
}